// round 14
// baseline (speedup 1.0000x reference)
#include <cuda_runtime.h>
#include <cuda_bf16.h>

// PointPillarsScatter gather v13 (v12 + block-level cellinfo reuse):
//  - d_cellinfo[cell] = (n<<24) | sum(pid); n==1 pid embedded (94.5% of occupied)
//  - Block = 512 threads = 16 warps: warp w handles channel group w, lanes are 32
//    consecutive cell groups. All 16 warps read the SAME 512B of cellinfo -> one L2
//    miss + 15 L1 hits (16x less L2 cellinfo traffic), and complementary 16B chunks
//    of the same feats rows (L2 line promotion).
//  - hot path: predicated n==1 float4 load into store regs; n>=2 inline rare block
//  - __launch_bounds__(512, 4) caps regs at 32 -> 64-warp occupancy ceiling
//
// Inputs:
//   d_in[0]: pillar_feats  float32 [B=4, P=30000, C=64]
//   d_in[1]: pillar_coords int32   [B=4, P=30000, 2]  (y, x)
// Output: float32 [4, 64, 512, 512]

#define BEV_H 512
#define BEV_W 512
#define HW (BEV_H * BEV_W)      // 262144 = 2^18
#define C_DIM 64
#define P_DIM 30000
#define B_DIM 4
#define CAP 8
#define NGRP ((B_DIM * HW) / 4) // 262144 groups of 4 cells

__device__ unsigned int   d_cellinfo[B_DIM * HW];     // 4 MB: (count<<24) | sum(pid)
__device__ unsigned short d_list[B_DIM * HW * CAP];   // 16 MB side lists (n>=2 only)

__global__ void pp_build_kernel(const int* __restrict__ coords) {
    int t = blockIdx.x * blockDim.x + threadIdx.x;
    if (t >= (B_DIM * P_DIM) / 2) return;

    int4 cc = reinterpret_cast<const int4*>(coords)[t];   // {y0,x0,y1,x1}
    int p0 = 2 * t, p1 = 2 * t + 1;

    int y0 = min(max(cc.x, 0), BEV_H - 1);
    int x0 = min(max(cc.y, 0), BEV_W - 1);
    int y1 = min(max(cc.z, 0), BEV_H - 1);
    int x1 = min(max(cc.w, 0), BEV_W - 1);

    int b0 = p0 / P_DIM, b1 = p1 / P_DIM;
    int pid0 = p0 - b0 * P_DIM, pid1 = p1 - b1 * P_DIM;
    int idx0 = b0 * HW + y0 * BEV_W + x0;
    int idx1 = b1 * HW + y1 * BEV_W + x1;

    unsigned old0 = atomicAdd(&d_cellinfo[idx0], (1u << 24) | (unsigned)pid0);
    unsigned old1 = atomicAdd(&d_cellinfo[idx1], (1u << 24) | (unsigned)pid1);
    unsigned pos0 = old0 >> 24, pos1 = old1 >> 24;
    if (pos0 < CAP) d_list[(size_t)idx0 * CAP + pos0] = (unsigned short)pid0;
    if (pos1 < CAP) d_list[(size_t)idx1 * CAP + pos1] = (unsigned short)pid1;
}

__global__ __launch_bounds__(512, 4) void pp_gather_kernel(const float* __restrict__ feats,
                                                           float* __restrict__ out) {
    // Block covers 32 consecutive cell groups x all 16 channel groups.
    int lane = threadIdx.x & 31;          // cell-group offset within block
    int chg  = threadIdx.x >> 5;          // channel group 0..15 (warp index)
    int grp  = (blockIdx.x << 5) + lane;  // cell group (consecutive across warp)

    int idx0  = grp << 2;
    int b     = idx0 >> 18;
    int cell0 = idx0 & (HW - 1);

    // 16 warps of this block read the same 512B: 1 L2 miss, 15 L1 hits.
    uint4 wv = *reinterpret_cast<const uint4*>(&d_cellinfo[idx0]);
    unsigned w[4] = {wv.x, wv.y, wv.z, wv.w};

    const float* fb = feats + (size_t)b * P_DIM * C_DIM + (chg << 2);

    // Hot path: predicated n==1 load directly into the store registers.
    float4 a[4];
    #pragma unroll
    for (int ci = 0; ci < 4; ci++) {
        float4 v = make_float4(0.f, 0.f, 0.f, 0.f);
        if ((w[ci] >> 24) == 1) {
            unsigned pid = w[ci] & 0xFFFFFFu;
            v = *reinterpret_cast<const float4*>(fb + (size_t)pid * C_DIM);
        }
        a[ci] = v;
    }

    // Rare path (0.65% of cells): inline multi-pillar sum from the side list.
    if (((w[0] | w[1] | w[2] | w[3]) >> 24) > 1) {
        #pragma unroll
        for (int ci = 0; ci < 4; ci++) {
            int n = (int)(w[ci] >> 24);
            if (n < 2) continue;
            n = min(n, CAP);
            float4 s = make_float4(0.f, 0.f, 0.f, 0.f);
            const unsigned short* lst = &d_list[(size_t)(idx0 + ci) * CAP];
            for (int i = 0; i < n; i++) {
                float4 v = *reinterpret_cast<const float4*>(fb + (size_t)lst[i] * C_DIM);
                s.x += v.x; s.y += v.y; s.z += v.z; s.w += v.w;
            }
            a[ci] = s;
        }
    }

    float* o = out + ((size_t)b * C_DIM + (size_t)(chg << 2)) * HW + cell0;
    __stcs(reinterpret_cast<float4*>(o + 0 * (size_t)HW), make_float4(a[0].x, a[1].x, a[2].x, a[3].x));
    __stcs(reinterpret_cast<float4*>(o + 1 * (size_t)HW), make_float4(a[0].y, a[1].y, a[2].y, a[3].y));
    __stcs(reinterpret_cast<float4*>(o + 2 * (size_t)HW), make_float4(a[0].z, a[1].z, a[2].z, a[3].z));
    __stcs(reinterpret_cast<float4*>(o + 3 * (size_t)HW), make_float4(a[0].w, a[1].w, a[2].w, a[3].w));
}

extern "C" void kernel_launch(void* const* d_in, const int* in_sizes, int n_in,
                              void* d_out, int out_size) {
    const float* feats  = (const float*)d_in[0];
    const int*   coords = (const int*)d_in[1];
    float*       out    = (float*)d_out;

    // Zero the fused cell words (4 MB, graph-capturable)
    void* info_ptr = nullptr;
    cudaGetSymbolAddress(&info_ptr, d_cellinfo);
    cudaMemsetAsync(info_ptr, 0, (size_t)B_DIM * HW * sizeof(unsigned int));

    int n_pairs = (B_DIM * P_DIM) / 2;             // 60,000 threads, 2 pillars each
    pp_build_kernel<<<(n_pairs + 255) / 256, 256>>>(coords);

    pp_gather_kernel<<<NGRP / 32, 512>>>(feats, out);   // 8192 blocks x 512 threads
}